// round 16
// baseline (speedup 1.0000x reference)
#include <cuda_runtime.h>
#include <cuda_bf16.h>
#include <math.h>
#include <stdint.h>

// ---------------- problem constants ----------------
#define B_    32
#define N_    4096
#define C_    128
#define MODES_ 32
#define L_    4
#define KIN_  256
#define KM_   64
#define CC_   (C_*C_)
#define OUT_  (C_*C_*MODES_)   // 524288
#define KAUG_ (C_ + 2*MODES_)  // 192
#define ROWS_ (B_*C_)          // 4096
#define KSEG_ 8
#define WSPLIT_ 2              // wspec i-split

// ---------------- scratch ----------------
__device__ __nv_bfloat16 d_xh0[ROWS_*N_];
__device__ __nv_bfloat16 d_xl0[ROWS_*N_];
__device__ __nv_bfloat16 d_xh1[ROWS_*N_];
__device__ __nv_bfloat16 d_xl1[ROWS_*N_];
__device__ __nv_bfloat16 d_ftabh[2*MODES_*N_];
__device__ __nv_bfloat16 d_ftabl[2*MODES_*N_];
__device__ __nv_bfloat16 d_itabh[2*MODES_*N_];
__device__ __nv_bfloat16 d_itabl[2*MODES_*N_];
__device__ float d_hg[L_*B_*KM_];
__device__ float d_hl[L_*B_*KM_];
__device__ float d_xft[ROWS_*2*MODES_];
__device__ float d_dftp[KSEG_*ROWS_*2*MODES_];   // dft partials; reused for wspec partials
__device__ __nv_bfloat16 d_Ahg[B_*C_*KAUG_];
__device__ __nv_bfloat16 d_Alg[B_*C_*KAUG_];
__device__ __nv_bfloat16 d_w1h[CC_];             // fc1_w transposed [h][c], hi
__device__ __nv_bfloat16 d_w1l[CC_];             // lo

#define WCP_Q 262144   // 32*128*64 floats per i-half of wspec partials

__device__ __forceinline__ float gelu_f(float x) {
    return 0.5f * x * (1.0f + erff(x * 0.70710678118654752f));
}

// ---------------- mma/ldmatrix/cp.async helpers ----------------
__device__ __forceinline__ uint32_t s2u(const void* p) {
    return (uint32_t)__cvta_generic_to_shared(p);
}
__device__ __forceinline__ void ldm_x4(uint32_t* r, uint32_t addr) {
    asm volatile("ldmatrix.sync.aligned.m8n8.x4.shared.b16 {%0,%1,%2,%3}, [%4];"
                 : "=r"(r[0]), "=r"(r[1]), "=r"(r[2]), "=r"(r[3]) : "r"(addr));
}
__device__ __forceinline__ void ldm_x4t(uint32_t* r, uint32_t addr) {
    asm volatile("ldmatrix.sync.aligned.m8n8.x4.trans.shared.b16 {%0,%1,%2,%3}, [%4];"
                 : "=r"(r[0]), "=r"(r[1]), "=r"(r[2]), "=r"(r[3]) : "r"(addr));
}
__device__ __forceinline__ void ldm_x2t(uint32_t* r, uint32_t addr) {
    asm volatile("ldmatrix.sync.aligned.m8n8.x2.trans.shared.b16 {%0,%1}, [%2];"
                 : "=r"(r[0]), "=r"(r[1]) : "r"(addr));
}
__device__ __forceinline__ void mma_bf16(float* d, const uint32_t* a,
                                         uint32_t b0, uint32_t b1) {
    asm volatile("mma.sync.aligned.m16n8k16.row.col.f32.bf16.bf16.f32 "
                 "{%0,%1,%2,%3}, {%4,%5,%6,%7}, {%8,%9}, {%0,%1,%2,%3};"
                 : "+f"(d[0]), "+f"(d[1]), "+f"(d[2]), "+f"(d[3])
                 : "r"(a[0]), "r"(a[1]), "r"(a[2]), "r"(a[3]), "r"(b0), "r"(b1));
}
__device__ __forceinline__ void cpa(uint32_t dst, const void* src) {
    asm volatile("cp.async.cg.shared.global [%0], [%1], 16;" :: "r"(dst), "l"(src));
}
#define CPA_COMMIT() asm volatile("cp.async.commit_group;")
#define CPA_WAIT(n)  asm volatile("cp.async.wait_group %0;" :: "n"(n))

__device__ __forceinline__ void bsplit(float v, __nv_bfloat16& h, __nv_bfloat16& l) {
    h = __float2bfloat16_rn(v);
    l = __float2bfloat16_rn(v - __bfloat162float(h));
}

// ---------------- tables ----------------
__global__ void table_kernel()
{
    int idx = blockIdx.x * 256 + threadIdx.x;
    if (idx >= 2*MODES_*N_) return;
    int m  = idx / N_;
    int n  = idx - m * N_;
    int mm = (m < MODES_) ? m : m - MODES_;
    float ang = 6.283185307179586f * (float)((mm * n) & (N_ - 1)) / (float)N_;
    float s, c;
    sincosf(ang, &s, &c);
    float fv = (m < MODES_) ? c : -s;
    __nv_bfloat16 h, l;
    bsplit(fv, h, l);
    d_ftabh[idx] = h;
    d_ftabl[idx] = l;
    float v;
    if (m < MODES_) v = (((m == 0) ? 1.0f : 2.0f) / (float)N_) * c;
    else            v = (mm == 0) ? 0.0f : (-2.0f / (float)N_) * s;
    bsplit(v, h, l);
    d_itabh[idx] = h;
    d_itabl[idx] = l;
}

// ---------------- w1 transpose + split (once) ----------------
__global__ void w1split_kernel(const float* __restrict__ w1)
{
    int idx = blockIdx.x * 256 + threadIdx.x;   // CC_
    int c = idx >> 7, h = idx & 127;
    float v = w1[idx];                           // w1[c][h]
    __nv_bfloat16 hh, ll;
    bsplit(v, hh, ll);
    d_w1h[h * C_ + c] = hh;
    d_w1l[h * C_ + c] = ll;
}

// ---------------- fc0 -> xh0/xl0 (vectorized: 8 n per thread) ----------------
__global__ void fc0_kernel(const float* __restrict__ x,
                           const float* __restrict__ w,
                           const float* __restrict__ bias)
{
    int idx = blockIdx.x * 256 + threadIdx.x;   // over ROWS_*N_/8
    int b = idx / (C_ * (N_ / 8));
    int rem = idx - b * (C_ * (N_ / 8));
    int c = rem / (N_ / 8);
    int n8 = rem - c * (N_ / 8);

    float w0 = w[c], w1v = w[C_ + c], w2v = w[2 * C_ + c], bz = bias[c];

    const float4* xp4 = (const float4*)(x + ((size_t)b * N_ + n8 * 8) * 3);
    float4 q0 = xp4[0], q1 = xp4[1], q2 = xp4[2];
    float4 q3 = xp4[3], q4 = xp4[4], q5 = xp4[5];
    float vv[24] = {q0.x,q0.y,q0.z,q0.w, q1.x,q1.y,q1.z,q1.w,
                    q2.x,q2.y,q2.z,q2.w, q3.x,q3.y,q3.z,q3.w,
                    q4.x,q4.y,q4.z,q4.w, q5.x,q5.y,q5.z,q5.w};

    union { __nv_bfloat16 bb[8]; uint4 u; } uh, ul;
    #pragma unroll
    for (int j = 0; j < 8; j++) {
        float v = bz + vv[j*3] * w0 + vv[j*3+1] * w1v + vv[j*3+2] * w2v;
        bsplit(v, uh.bb[j], ul.bb[j]);
    }
    size_t o = ((size_t)(b * C_ + c)) * N_ + n8 * 8;
    *(uint4*)&d_xh0[o] = uh.u;
    *(uint4*)&d_xl0[o] = ul.u;
}

// ---------------- hg/hl: 256 threads, 4-way j-segment split ----------------
__global__ void hgl_kernel(const float* __restrict__ y,
                           const float* __restrict__ g1w, const float* __restrict__ g1b,
                           const float* __restrict__ l1w, const float* __restrict__ l1b)
{
    int b = blockIdx.x, which = blockIdx.y, l = blockIdx.z;
    __shared__ float ys[KIN_];
    __shared__ float red[4][KM_];
    int t = threadIdx.x;
    int k = t & 63, seg = t >> 6;
    for (int j = t; j < KIN_; j += 256) ys[j] = y[b * KIN_ + j];
    __syncthreads();
    const float* w = (which ? l1w : g1w) + (size_t)l * KIN_ * KM_ + seg * 64 * KM_;
    float acc = 0.0f;
    #pragma unroll 16
    for (int j = 0; j < 64; j++) acc += ys[seg * 64 + j] * w[j * KM_ + k];
    red[seg][k] = acc;
    __syncthreads();
    if (t < KM_) {
        const float* bb = (which ? l1b : g1b) + l * KM_;
        float v = red[0][t] + red[1][t] + red[2][t] + red[3][t] + bb[t];
        float g = gelu_f(v);
        float* dst = which ? d_hl : d_hg;
        dst[l * B_ * KM_ + b * KM_ + t] = g;
    }
}

// ---------------- forward DFT via mma.sync bf16x3, cp.async double-buffered ----------------
#define DFT_AH 0
#define DFT_AL 20480
#define DFT_BH 40960
#define DFT_BL 51200
#define DFT_SM 61440
#define DFT_ABUF 10240
#define DFT_BBUF 5120

__global__ void __launch_bounds__(256) dft_mma_kernel(int in_x1)
{
    extern __shared__ char smem[];
    uint32_t sb = s2u(smem);
    const __nv_bfloat16* __restrict__ xh = in_x1 ? d_xh1 : d_xh0;
    const __nv_bfloat16* __restrict__ xl = in_x1 ? d_xl1 : d_xl0;

    int r0 = blockIdx.x * 128;
    int K0 = blockIdx.y * (N_ / KSEG_);
    int t = threadIdx.x, wid = t >> 5, lane = t & 31;

    float acc[8][4];
    #pragma unroll
    for (int j = 0; j < 8; j++)
        #pragma unroll
        for (int q = 0; q < 4; q++) acc[j][q] = 0.0f;

    auto stage = [&](int c, int bf) {
        #pragma unroll
        for (int i = 0; i < 2; i++) {
            int f = t + 256 * i;
            int o = f >> 2, q = f & 3;
            size_t g = (size_t)(r0 + o) * N_ + K0 + c * 32 + q * 8;
            cpa(sb + DFT_AH + bf * DFT_ABUF + o * 80 + q * 16, xh + g);
            cpa(sb + DFT_AL + bf * DFT_ABUF + o * 80 + q * 16, xl + g);
        }
        {
            int j = t >> 2, q = t & 3;
            size_t g = (size_t)j * N_ + K0 + c * 32 + q * 8;
            cpa(sb + DFT_BH + bf * DFT_BBUF + j * 80 + q * 16, d_ftabh + g);
            cpa(sb + DFT_BL + bf * DFT_BBUF + j * 80 + q * 16, d_ftabl + g);
        }
    };

    stage(0, 0);
    CPA_COMMIT();

    const int NCHUNK = (N_ / KSEG_) / 32;   // 16
    for (int c = 0; c < NCHUNK; c++) {
        int bf = c & 1;
        if (c < NCHUNK - 1) {
            stage(c + 1, bf ^ 1);
            CPA_COMMIT();
            CPA_WAIT(1);
        } else {
            CPA_WAIT(0);
        }
        __syncthreads();

        #pragma unroll
        for (int ks = 0; ks < 32; ks += 16) {
            uint32_t ah[4], al[4];
            {
                int r = wid * 16 + (lane & 15);
                uint32_t off = (uint32_t)r * 80 + (uint32_t)(ks + ((lane >> 4) << 3)) * 2;
                ldm_x4(ah, sb + DFT_AH + bf * DFT_ABUF + off);
                ldm_x4(al, sb + DFT_AL + bf * DFT_ABUF + off);
            }
            #pragma unroll
            for (int nb = 0; nb < 4; nb++) {
                int jr = nb * 16 + (lane & 7) + ((lane >> 4) << 3);
                int kc = ks + (((lane >> 3) & 1) << 3);
                uint32_t off = (uint32_t)jr * 80 + (uint32_t)kc * 2;
                uint32_t bh[4], bl[4];
                ldm_x4(bh, sb + DFT_BH + bf * DFT_BBUF + off);
                ldm_x4(bl, sb + DFT_BL + bf * DFT_BBUF + off);
                mma_bf16(acc[nb*2],     ah, bh[0], bh[1]);
                mma_bf16(acc[nb*2],     ah, bl[0], bl[1]);
                mma_bf16(acc[nb*2],     al, bh[0], bh[1]);
                mma_bf16(acc[nb*2 + 1], ah, bh[2], bh[3]);
                mma_bf16(acc[nb*2 + 1], ah, bl[2], bl[3]);
                mma_bf16(acc[nb*2 + 1], al, bh[2], bh[3]);
            }
        }
        __syncthreads();
    }

    float* dst = d_dftp + ((size_t)blockIdx.y * ROWS_ + r0) * 64;
    int row = wid * 16 + (lane >> 2);
    #pragma unroll
    for (int j = 0; j < 8; j++) {
        int col = j * 8 + (lane & 3) * 2;
        *(float2*)&dst[(size_t)row * 64 + col]       = make_float2(acc[j][0], acc[j][1]);
        *(float2*)&dst[(size_t)(row + 8) * 64 + col] = make_float2(acc[j][2], acc[j][3]);
    }
}

// ---------------- FUSED dft_reduce + wlin (independent work, one launch) ----------------
// blocks [0, 1024): reduce d_dftp -> d_xft
// blocks [1024, 1088): wlin -> d_Ahg/d_Alg cols 0..127
__global__ void __launch_bounds__(256) reduce_wlin_kernel(
    const float* __restrict__ l2w_l, const float* __restrict__ l2b_l, int l)
{
    __shared__ float hs[B_ * KM_];
    int t = threadIdx.x;
    if (blockIdx.x < (ROWS_ * 64) / 256) {
        int idx = blockIdx.x * 256 + t;
        float s = 0.0f;
        #pragma unroll
        for (int seg = 0; seg < KSEG_; seg++) s += d_dftp[(size_t)seg * ROWS_ * 64 + idx];
        d_xft[idx] = s;
        return;
    }
    // ---- wlin part ----
    int wb = blockIdx.x - (ROWS_ * 64) / 256;
    for (int i = t; i < B_ * KM_; i += 256) hs[i] = d_hl[l * B_ * KM_ + i];
    __syncthreads();
    int col = wb * 256 + t;
    int o = col >> 7, ii = col & 127;
    float bias = l2b_l[col];
    float acc[B_];
    #pragma unroll
    for (int b = 0; b < B_; b++) acc[b] = bias;
    #pragma unroll 4
    for (int k = 0; k < KM_; k++) {
        float g = l2w_l[(size_t)k * CC_ + col];
        #pragma unroll
        for (int b = 0; b < B_; b++) acc[b] += hs[b * KM_ + k] * g;
    }
    #pragma unroll
    for (int b = 0; b < B_; b++) {
        __nv_bfloat16 h, lo;
        bsplit(acc[b], h, lo);
        size_t idx = ((size_t)(b * C_ + o)) * KAUG_ + ii;
        d_Ahg[idx] = h;
        d_Alg[idx] = lo;
    }
}

// ---------------- FUSED wspec + spectral contraction, cp.async depth-4 G ring ----------------
// grid (C_, WSPLIT_): blockIdx.x = o, blockIdx.y = ih (i half, 32 p2-iters each).
// Partials -> d_dftp half ih. Warp layout: iw = i-parity (2), nq = mode-quarter (4).
#define WS_AH 0
#define WS_AL 5120
#define WS_GH 10240
#define WS_GL 20480
#define WS_XS 30720
#define WS_GF 47104
#define WS_GFSTG 16640
#define WS_RING 4
#define WS_SM (WS_GF + WS_RING * WS_GFSTG)   // 113664

__global__ void __launch_bounds__(256) wspec_contract_kernel(
    const float* __restrict__ g2w_l, const float* __restrict__ g2b_l, int l)
{
    extern __shared__ char smem[];
    __nv_bfloat16* Ahs = (__nv_bfloat16*)(smem + WS_AH);   // [32][80]
    __nv_bfloat16* Als = (__nv_bfloat16*)(smem + WS_AL);
    __nv_bfloat16* Gh  = (__nv_bfloat16*)(smem + WS_GH);   // [2][80][32]
    __nv_bfloat16* Gl  = (__nv_bfloat16*)(smem + WS_GL);
    float*         Xs  = (float*)(smem + WS_XS);           // [2][32][64]
    uint32_t sb = s2u(smem);

    int o = blockIdx.x;
    int ih = blockIdx.y;
    int t = threadIdx.x, lane = t & 31, wid = t >> 5;
    int iw = wid & 1, nq = wid >> 1;   // i-parity, mode-quarter

    // stage A = [hg | 1 | 0...] split hi/lo
    for (int idx = t; idx < 32 * 80; idx += 256) {
        int b = idx / 80, k = idx - b * 80;
        float v = (k < 64) ? d_hg[l * B_ * KM_ + b * 64 + k]
                           : (k == 64 ? 1.0f : 0.0f);
        __nv_bfloat16 h, lo;
        bsplit(v, h, lo);
        Ahs[b * 80 + k] = h;
        Als[b * 80 + k] = lo;
    }
    // zero G rows 65..79 (both parities) once
    for (int idx = t; idx < 2 * 15 * 32; idx += 256) {
        int p = idx / (15 * 32), r = idx - p * (15 * 32);
        int row = 65 + (r >> 5), m = r & 31;
        Gh[(p * 80 + row) * 32 + m] = __float2bfloat16(0.0f);
        Gl[(p * 80 + row) * 32 + m] = __float2bfloat16(0.0f);
    }
    __syncthreads();

    // preload A fragments for BOTH m16 halves (constant over i)
    uint32_t afh[2][5][4], afl[2][5][4];
    #pragma unroll
    for (int mi = 0; mi < 2; mi++)
        #pragma unroll
        for (int kt = 0; kt < 5; kt++) {
            int r = mi * 16 + (lane & 15);
            uint32_t off = ((uint32_t)r * 80 + kt * 16 + ((lane >> 4) << 3)) * 2;
            ldm_x4(afh[mi][kt], sb + WS_AH + off);
            ldm_x4(afl[mi][kt], sb + WS_AL + off);
        }

    float accr[2][4], acci[2][4];
    #pragma unroll
    for (int mi = 0; mi < 2; mi++)
        #pragma unroll
        for (int q = 0; q < 4; q++) { accr[mi][q] = 0.0f; acci[mi][q] = 0.0f; }

    // cp.async G-stage issuer: 1040 16B chunks (2 i x 65 rows x 8 segs)
    auto issue_g = [&](int p2, int buf) {
        #pragma unroll
        for (int j = 0; j < 5; j++) {
            int idx = t + j * 256;
            if (idx < 1040) {
                int p = (idx >= 520) ? 1 : 0;
                int r = idx - p * 520;
                int row = r >> 3, seg = r & 7;
                int i = p2 * 2 + p;
                const float* src = (row < 64)
                    ? (g2w_l + (size_t)row * OUT_ + (size_t)i * (C_ * MODES_) + o * MODES_ + seg * 4)
                    : (g2b_l + (size_t)i * (C_ * MODES_) + o * MODES_ + seg * 4);
                cpa(sb + WS_GF + buf * WS_GFSTG + p * 8320 + row * 128 + seg * 16, src);
            }
        }
        CPA_COMMIT();
    };

    float4 x_r[4];
    auto xprefetch = [&](int p2) {
        #pragma unroll
        for (int j = 0; j < 4; j++) {
            int idx = t + j * 256;
            int p = idx >> 9, r = idx & 511;
            int b = r >> 4, seg = r & 15;
            int i = p2 * 2 + p;
            x_r[j] = *(const float4*)&d_xft[((size_t)(b * C_) + i) * 64 + seg * 4];
        }
    };

    const int NIT = 64 / WSPLIT_;   // 32
    int p2_begin = ih * NIT;
    issue_g(p2_begin + 0, 0);
    issue_g(p2_begin + 1, 1);
    issue_g(p2_begin + 2, 2);
    issue_g(p2_begin + 3, 3);
    xprefetch(p2_begin);

    for (int c = 0; c < NIT; c++) {
        int p2 = p2_begin + c;
        CPA_WAIT(3);          // stage c landed (3 stages still in flight)
        __syncthreads();      // + prev MMA done reading Gh/Gl

        // split G fp32 (ring buf c%4) -> Gh/Gl bf16; store X regs -> Xs
        {
            int buf = c % WS_RING;
            #pragma unroll
            for (int j = 0; j < 5; j++) {
                int idx = t + j * 256;
                if (idx < 1040) {
                    int p = (idx >= 520) ? 1 : 0;
                    int r = idx - p * 520;
                    int row = r >> 3, seg = r & 7;
                    float4 v = *(float4*)(smem + WS_GF + buf * WS_GFSTG + p * 8320 + row * 128 + seg * 16);
                    __nv_bfloat16 h0,l0,h1,l1,h2,l2,h3,l3;
                    bsplit(v.x,h0,l0); bsplit(v.y,h1,l1);
                    bsplit(v.z,h2,l2); bsplit(v.w,h3,l3);
                    int gbase = (p * 80 + row) * 32 + seg * 4;
                    *(__nv_bfloat162*)&Gh[gbase]     = __halves2bfloat162(h0, h1);
                    *(__nv_bfloat162*)&Gh[gbase + 2] = __halves2bfloat162(h2, h3);
                    *(__nv_bfloat162*)&Gl[gbase]     = __halves2bfloat162(l0, l1);
                    *(__nv_bfloat162*)&Gl[gbase + 2] = __halves2bfloat162(l2, l3);
                }
            }
            #pragma unroll
            for (int j = 0; j < 4; j++) {
                int idx = t + j * 256;
                int p = idx >> 9, r = idx & 511;
                int b = r >> 4, seg = r & 15;
                *(float4*)&Xs[(p * 32 + b) * 64 + seg * 4] = x_r[j];
            }
        }
        __syncthreads();      // split visible; ring buf c%4 free

        if (c < NIT - WS_RING) issue_g(p2 + WS_RING, (c + WS_RING) % WS_RING);
        else                   CPA_COMMIT();   // keep group accounting uniform
        if (c < NIT - 1) xprefetch(p2 + 1);

        // W = A x G (bf16x3): each warp covers 32 b x 8 modes, B-frags read ONCE
        float W[2][4];
        #pragma unroll
        for (int mi = 0; mi < 2; mi++)
            #pragma unroll
            for (int q = 0; q < 4; q++) W[mi][q] = 0.0f;

        uint32_t gbase_h = sb + WS_GH + (uint32_t)iw * 80 * 32 * 2;
        uint32_t gbase_l = sb + WS_GL + (uint32_t)iw * 80 * 32 * 2;
        #pragma unroll
        for (int kt = 0; kt < 5; kt++) {
            uint32_t off = ((uint32_t)(kt * 16 + (lane & 15)) * 32 + nq * 8) * 2;
            uint32_t bh[2], bl[2];
            ldm_x2t(bh, gbase_h + off);
            ldm_x2t(bl, gbase_l + off);
            #pragma unroll
            for (int mi = 0; mi < 2; mi++) {
                mma_bf16(W[mi], afh[mi][kt], bh[0], bh[1]);
                mma_bf16(W[mi], afh[mi][kt], bl[0], bl[1]);
                mma_bf16(W[mi], afl[mi][kt], bh[0], bh[1]);
            }
        }

        int m0 = nq * 8 + (lane & 3) * 2;
        #pragma unroll
        for (int mi = 0; mi < 2; mi++) {
            int b0 = mi * 16 + (lane >> 2);
            float2 xr0 = *(float2*)&Xs[(iw * 32 + b0) * 64 + m0];
            float2 xi0 = *(float2*)&Xs[(iw * 32 + b0) * 64 + 32 + m0];
            float2 xr1 = *(float2*)&Xs[(iw * 32 + b0 + 8) * 64 + m0];
            float2 xi1 = *(float2*)&Xs[(iw * 32 + b0 + 8) * 64 + 32 + m0];
            accr[mi][0] += W[mi][0] * xr0.x;  accr[mi][1] += W[mi][1] * xr0.y;
            accr[mi][2] += W[mi][2] * xr1.x;  accr[mi][3] += W[mi][3] * xr1.y;
            acci[mi][0] += W[mi][0] * xi0.x;  acci[mi][1] += W[mi][1] * xi0.y;
            acci[mi][2] += W[mi][2] * xi1.x;  acci[mi][3] += W[mi][3] * xi1.y;
        }
    }

    // reduce across iw parities (reuse Xs region), write partials to d_dftp half ih
    __syncthreads();
    int m0 = nq * 8 + (lane & 3) * 2;
    if (iw == 1) {
        #pragma unroll
        for (int mi = 0; mi < 2; mi++) {
            int b0 = mi * 16 + (lane >> 2);
            Xs[b0 * 64 + m0]              = accr[mi][0];
            Xs[b0 * 64 + m0 + 1]          = accr[mi][1];
            Xs[(b0 + 8) * 64 + m0]        = accr[mi][2];
            Xs[(b0 + 8) * 64 + m0 + 1]    = accr[mi][3];
            Xs[b0 * 64 + 32 + m0]         = acci[mi][0];
            Xs[b0 * 64 + 32 + m0 + 1]     = acci[mi][1];
            Xs[(b0 + 8) * 64 + 32 + m0]   = acci[mi][2];
            Xs[(b0 + 8) * 64 + 32 + m0+1] = acci[mi][3];
        }
    }
    __syncthreads();
    if (iw == 0) {
        #pragma unroll
        for (int mi = 0; mi < 2; mi++) {
            int b0 = mi * 16 + (lane >> 2);
            float r00 = accr[mi][0] + Xs[b0 * 64 + m0];
            float r01 = accr[mi][1] + Xs[b0 * 64 + m0 + 1];
            float r10 = accr[mi][2] + Xs[(b0 + 8) * 64 + m0];
            float r11 = accr[mi][3] + Xs[(b0 + 8) * 64 + m0 + 1];
            float i00 = acci[mi][0] + Xs[b0 * 64 + 32 + m0];
            float i01 = acci[mi][1] + Xs[b0 * 64 + 32 + m0 + 1];
            float i10 = acci[mi][2] + Xs[(b0 + 8) * 64 + 32 + m0];
            float i11 = acci[mi][3] + Xs[(b0 + 8) * 64 + 32 + m0 + 1];
            float* P0 = d_dftp + (size_t)ih * WCP_Q + ((size_t)(b0 * C_ + o)) * 64;
            float* P1 = d_dftp + (size_t)ih * WCP_Q + ((size_t)((b0 + 8) * C_ + o)) * 64;
            *(float2*)&P0[m0]      = make_float2(r00, r01);
            *(float2*)&P1[m0]      = make_float2(r10, r11);
            *(float2*)&P0[32 + m0] = make_float2(i00, i01);
            *(float2*)&P1[32 + m0] = make_float2(i10, i11);
        }
    }
}

// ---------------- combine wspec halves -> d_Ahg/d_Alg cols 128..191 ----------------
__global__ void asplit_kernel()
{
    int idx = blockIdx.x * 256 + threadIdx.x;   // B_*C_*64
    int row = idx >> 6;
    int tt = idx & 63;
    float v = d_dftp[(size_t)row * 64 + tt] + d_dftp[WCP_Q + (size_t)row * 64 + tt];
    __nv_bfloat16 h, l;
    bsplit(v, h, l);
    size_t g = (size_t)row * KAUG_ + C_ + tt;
    d_Ahg[g] = h;
    d_Alg[g] = l;
}

// ---------------- layer GEMM via mma.sync bf16x3, cp.async double-buffered ----------------
#define LAY_AH 0
#define LAY_AL 20480
#define LAY_BH 40960
#define LAY_BL 58368
#define LAY_SM 75776
#define LAY_ABUF 10240
#define LAY_BBUF 8704

__global__ void __launch_bounds__(256, 2) layer_mma_kernel(int in_x1, int do_gelu)
{
    extern __shared__ char smem[];
    uint32_t sb = s2u(smem);
    const __nv_bfloat16* __restrict__ xh = in_x1 ? d_xh1 : d_xh0;
    const __nv_bfloat16* __restrict__ xl = in_x1 ? d_xl1 : d_xl0;
    __nv_bfloat16* __restrict__ yh = in_x1 ? d_xh0 : d_xh1;
    __nv_bfloat16* __restrict__ yl = in_x1 ? d_xl0 : d_xl1;

    int b = blockIdx.y, n0 = blockIdx.x * 128;
    int t = threadIdx.x, wid = t >> 5, lane = t & 31;
    int wm = wid & 3, wn = wid >> 2;

    const __nv_bfloat16* Ahb = d_Ahg + (size_t)b * C_ * KAUG_;
    const __nv_bfloat16* Alb = d_Alg + (size_t)b * C_ * KAUG_;
    size_t xbase = (size_t)b * C_ * N_;

    float acc[2][8][4];
    #pragma unroll
    for (int mi = 0; mi < 2; mi++)
        #pragma unroll
        for (int j = 0; j < 8; j++)
            #pragma unroll
            for (int q = 0; q < 4; q++) acc[mi][j][q] = 0.0f;

    auto stage = [&](int c, int bf) {
        #pragma unroll
        for (int i = 0; i < 2; i++) {
            int f = t + 256 * i;
            int o = f >> 2, q = f & 3;
            size_t g = (size_t)o * KAUG_ + c * 32 + q * 8;
            cpa(sb + LAY_AH + bf * LAY_ABUF + o * 80 + q * 16, Ahb + g);
            cpa(sb + LAY_AL + bf * LAY_ABUF + o * 80 + q * 16, Alb + g);
        }
        #pragma unroll
        for (int i = 0; i < 2; i++) {
            int f = t + 256 * i;
            int kk = f >> 4, q = f & 15;
            int kg = c * 32 + kk;
            const __nv_bfloat16 *rh, *rl;
            if (kg < C_) {
                rh = xh + xbase + (size_t)kg * N_ + n0;
                rl = xl + xbase + (size_t)kg * N_ + n0;
            } else {
                rh = d_itabh + (size_t)(kg - C_) * N_ + n0;
                rl = d_itabl + (size_t)(kg - C_) * N_ + n0;
            }
            cpa(sb + LAY_BH + bf * LAY_BBUF + kk * 272 + q * 16, rh + q * 8);
            cpa(sb + LAY_BL + bf * LAY_BBUF + kk * 272 + q * 16, rl + q * 8);
        }
    };

    stage(0, 0);
    CPA_COMMIT();

    for (int c = 0; c < 6; c++) {
        int bf = c & 1;
        if (c < 5) {
            stage(c + 1, bf ^ 1);
            CPA_COMMIT();
            CPA_WAIT(1);
        } else {
            CPA_WAIT(0);
        }
        __syncthreads();

        #pragma unroll
        for (int ks = 0; ks < 32; ks += 16) {
            uint32_t ah[2][4], al[2][4];
            #pragma unroll
            for (int mi = 0; mi < 2; mi++) {
                int r = wm * 32 + mi * 16 + (lane & 15);
                uint32_t off = (uint32_t)r * 80 + (uint32_t)(ks + ((lane >> 4) << 3)) * 2;
                ldm_x4(ah[mi], sb + LAY_AH + bf * LAY_ABUF + off);
                ldm_x4(al[mi], sb + LAY_AL + bf * LAY_ABUF + off);
            }
            #pragma unroll
            for (int nb = 0; nb < 4; nb++) {
                int kr = ks + (lane & 15);
                int nc = wn * 64 + nb * 16 + ((lane >> 4) << 3);
                uint32_t off = (uint32_t)kr * 272 + (uint32_t)nc * 2;
                uint32_t bh[4], bl[4];
                ldm_x4t(bh, sb + LAY_BH + bf * LAY_BBUF + off);
                ldm_x4t(bl, sb + LAY_BL + bf * LAY_BBUF + off);
                #pragma unroll
                for (int mi = 0; mi < 2; mi++) {
                    mma_bf16(acc[mi][nb*2],     ah[mi], bh[0], bh[1]);
                    mma_bf16(acc[mi][nb*2],     ah[mi], bl[0], bl[1]);
                    mma_bf16(acc[mi][nb*2],     al[mi], bh[0], bh[1]);
                    mma_bf16(acc[mi][nb*2 + 1], ah[mi], bh[2], bh[3]);
                    mma_bf16(acc[mi][nb*2 + 1], ah[mi], bl[2], bl[3]);
                    mma_bf16(acc[mi][nb*2 + 1], al[mi], bh[2], bh[3]);
                }
            }
        }
        __syncthreads();
    }

    #pragma unroll
    for (int mi = 0; mi < 2; mi++) {
        int o = wm * 32 + mi * 16 + (lane >> 2);
        #pragma unroll
        for (int j = 0; j < 8; j++) {
            int col = n0 + wn * 64 + j * 8 + (lane & 3) * 2;
            float v0 = acc[mi][j][0], v1 = acc[mi][j][1];
            float v2 = acc[mi][j][2], v3 = acc[mi][j][3];
            if (do_gelu) {
                v0 = gelu_f(v0); v1 = gelu_f(v1);
                v2 = gelu_f(v2); v3 = gelu_f(v3);
            }
            __nv_bfloat16 h0, l0, h1, l1, h2, l2, h3, l3;
            bsplit(v0, h0, l0); bsplit(v1, h1, l1);
            bsplit(v2, h2, l2); bsplit(v3, h3, l3);
            size_t p0 = xbase + (size_t)o * N_ + col;
            size_t p1 = xbase + (size_t)(o + 8) * N_ + col;
            *(__nv_bfloat162*)&yh[p0] = __halves2bfloat162(h0, h1);
            *(__nv_bfloat162*)&yl[p0] = __halves2bfloat162(l0, l1);
            *(__nv_bfloat162*)&yh[p1] = __halves2bfloat162(h2, h3);
            *(__nv_bfloat162*)&yl[p1] = __halves2bfloat162(l2, l3);
        }
    }
}

// ---------------- final MLP via mma.sync bf16x3 ----------------
#define FIN_OFF LAY_SM
#define FIN_SM  (LAY_SM + 2048)

__global__ void __launch_bounds__(256, 2) final_mma_kernel(
    const float* __restrict__ b1, const float* __restrict__ w2,
    const float* __restrict__ b2, const float* __restrict__ wx,
    float* __restrict__ out)
{
    extern __shared__ char smem[];
    uint32_t sb = s2u(smem);
    float* fin = (float*)(smem + FIN_OFF);   // [4][128]

    int b = blockIdx.y, n0 = blockIdx.x * 128;
    int t = threadIdx.x, wid = t >> 5, lane = t & 31;
    int wm = wid & 3, wn = wid >> 2;
    size_t xbase = (size_t)b * C_ * N_;

    float acc[2][8][4];
    #pragma unroll
    for (int mi = 0; mi < 2; mi++)
        #pragma unroll
        for (int j = 0; j < 8; j++)
            #pragma unroll
            for (int q = 0; q < 4; q++) acc[mi][j][q] = 0.0f;

    auto stage = [&](int c, int bf) {
        #pragma unroll
        for (int i = 0; i < 2; i++) {
            int f = t + 256 * i;
            int o = f >> 2, q = f & 3;
            size_t g = (size_t)o * C_ + c * 32 + q * 8;
            cpa(sb + LAY_AH + bf * LAY_ABUF + o * 80 + q * 16, d_w1h + g);
            cpa(sb + LAY_AL + bf * LAY_ABUF + o * 80 + q * 16, d_w1l + g);
        }
        #pragma unroll
        for (int i = 0; i < 2; i++) {
            int f = t + 256 * i;
            int kk = f >> 4, q = f & 15;
            int kg = c * 32 + kk;
            cpa(sb + LAY_BH + bf * LAY_BBUF + kk * 272 + q * 16,
                d_xh0 + xbase + (size_t)kg * N_ + n0 + q * 8);
            cpa(sb + LAY_BL + bf * LAY_BBUF + kk * 272 + q * 16,
                d_xl0 + xbase + (size_t)kg * N_ + n0 + q * 8);
        }
    };

    stage(0, 0);
    CPA_COMMIT();

    for (int c = 0; c < 4; c++) {
        int bf = c & 1;
        if (c < 3) {
            stage(c + 1, bf ^ 1);
            CPA_COMMIT();
            CPA_WAIT(1);
        } else {
            CPA_WAIT(0);
        }
        __syncthreads();

        #pragma unroll
        for (int ks = 0; ks < 32; ks += 16) {
            uint32_t ah[2][4], al[2][4];
            #pragma unroll
            for (int mi = 0; mi < 2; mi++) {
                int r = wm * 32 + mi * 16 + (lane & 15);
                uint32_t off = (uint32_t)r * 80 + (uint32_t)(ks + ((lane >> 4) << 3)) * 2;
                ldm_x4(ah[mi], sb + LAY_AH + bf * LAY_ABUF + off);
                ldm_x4(al[mi], sb + LAY_AL + bf * LAY_ABUF + off);
            }
            #pragma unroll
            for (int nb = 0; nb < 4; nb++) {
                int kr = ks + (lane & 15);
                int nc = wn * 64 + nb * 16 + ((lane >> 4) << 3);
                uint32_t off = (uint32_t)kr * 272 + (uint32_t)nc * 2;
                uint32_t bh[4], bl[4];
                ldm_x4t(bh, sb + LAY_BH + bf * LAY_BBUF + off);
                ldm_x4t(bl, sb + LAY_BL + bf * LAY_BBUF + off);
                #pragma unroll
                for (int mi = 0; mi < 2; mi++) {
                    mma_bf16(acc[mi][nb*2],     ah[mi], bh[0], bh[1]);
                    mma_bf16(acc[mi][nb*2],     ah[mi], bl[0], bl[1]);
                    mma_bf16(acc[mi][nb*2],     al[mi], bh[0], bh[1]);
                    mma_bf16(acc[mi][nb*2 + 1], ah[mi], bh[2], bh[3]);
                    mma_bf16(acc[mi][nb*2 + 1], ah[mi], bl[2], bl[3]);
                    mma_bf16(acc[mi][nb*2 + 1], al[mi], bh[2], bh[3]);
                }
            }
        }
        __syncthreads();
    }

    float p[8][2];
    #pragma unroll
    for (int j = 0; j < 8; j++) { p[j][0] = 0.0f; p[j][1] = 0.0f; }
    #pragma unroll
    for (int mi = 0; mi < 2; mi++) {
        int ra = wm * 32 + mi * 16 + (lane >> 2);
        float b1a = b1[ra], b1b = b1[ra + 8];
        float w2a = w2[ra], w2b = w2[ra + 8];
        #pragma unroll
        for (int j = 0; j < 8; j++) {
            p[j][0] += gelu_f(acc[mi][j][0] + b1a) * w2a + gelu_f(acc[mi][j][2] + b1b) * w2b;
            p[j][1] += gelu_f(acc[mi][j][1] + b1a) * w2a + gelu_f(acc[mi][j][3] + b1b) * w2b;
        }
    }
    #pragma unroll
    for (int off = 4; off < 32; off <<= 1) {
        #pragma unroll
        for (int j = 0; j < 8; j++) {
            p[j][0] += __shfl_xor_sync(0xFFFFFFFFu, p[j][0], off);
            p[j][1] += __shfl_xor_sync(0xFFFFFFFFu, p[j][1], off);
        }
    }
    if ((lane >> 2) == 0) {
        #pragma unroll
        for (int j = 0; j < 8; j++) {
            int col = wn * 64 + j * 8 + (lane & 3) * 2;
            fin[wm * 128 + col]     = p[j][0];
            fin[wm * 128 + col + 1] = p[j][1];
        }
    }
    __syncthreads();
    if (t < 128) {
        float v = fin[t] + fin[128 + t] + fin[256 + t] + fin[384 + t] + b2[0];
        out[(size_t)b * N_ + n0 + t] = v * wx[0];
    }
}

// ---------------- launch ----------------
extern "C" void kernel_launch(void* const* d_in, const int* in_sizes, int n_in,
                              void* d_out, int out_size)
{
    const float* x     = (const float*)d_in[0];
    const float* y     = (const float*)d_in[1];
    const float* fc0_w = (const float*)d_in[2];
    const float* fc0_b = (const float*)d_in[3];
    const float* g1_w  = (const float*)d_in[4];
    const float* g1_b  = (const float*)d_in[5];
    const float* g2_w  = (const float*)d_in[6];
    const float* g2_b  = (const float*)d_in[7];
    const float* l1_w  = (const float*)d_in[8];
    const float* l1_b  = (const float*)d_in[9];
    const float* l2_w  = (const float*)d_in[10];
    const float* l2_b  = (const float*)d_in[11];
    const float* fc1_w = (const float*)d_in[12];
    const float* fc1_b = (const float*)d_in[13];
    const float* fc2_w = (const float*)d_in[14];
    const float* fc2_b = (const float*)d_in[15];
    const float* wx    = (const float*)d_in[16];
    float* out = (float*)d_out;

    cudaFuncSetAttribute(dft_mma_kernel,
                         cudaFuncAttributeMaxDynamicSharedMemorySize, DFT_SM);
    cudaFuncSetAttribute(wspec_contract_kernel,
                         cudaFuncAttributeMaxDynamicSharedMemorySize, WS_SM);
    cudaFuncSetAttribute(layer_mma_kernel,
                         cudaFuncAttributeMaxDynamicSharedMemorySize, LAY_SM);
    cudaFuncSetAttribute(final_mma_kernel,
                         cudaFuncAttributeMaxDynamicSharedMemorySize, FIN_SM);

    table_kernel<<<(2*MODES_*N_)/256, 256>>>();
    w1split_kernel<<<CC_/256, 256>>>(fc1_w);
    fc0_kernel<<<(ROWS_*N_/8)/256, 256>>>(x, fc0_w, fc0_b);
    hgl_kernel<<<dim3(B_, 2, L_), 256>>>(y, g1_w, g1_b, l1_w, l1_b);

    for (int l = 0; l < L_; l++) {
        int in_x1 = l & 1;
        dft_mma_kernel<<<dim3(ROWS_/128, KSEG_), 256, DFT_SM>>>(in_x1);
        reduce_wlin_kernel<<<(ROWS_*64)/256 + CC_/256, 256>>>(
            l2_w + (size_t)l * KM_ * CC_, l2_b + (size_t)l * CC_, l);
        wspec_contract_kernel<<<dim3(C_, WSPLIT_), 256, WS_SM>>>(
            g2_w + (size_t)l * KM_ * OUT_, g2_b + (size_t)l * OUT_, l);
        asplit_kernel<<<(B_*C_*64)/256, 256>>>();
        layer_mma_kernel<<<dim3(N_/128, B_), 256, LAY_SM>>>(in_x1, (l < L_ - 1) ? 1 : 0);
    }

    final_mma_kernel<<<dim3(N_/128, B_), 256, FIN_SM>>>(fc1_b, fc2_w, fc2_b, wx, out);
}

// round 17
// speedup vs baseline: 1.0450x; 1.0450x over previous
#include <cuda_runtime.h>
#include <cuda_bf16.h>
#include <math.h>
#include <stdint.h>

// ---------------- problem constants ----------------
#define B_    32
#define N_    4096
#define C_    128
#define MODES_ 32
#define L_    4
#define KIN_  256
#define KM_   64
#define CC_   (C_*C_)
#define OUT_  (C_*C_*MODES_)   // 524288
#define KAUG_ (C_ + 2*MODES_)  // 192
#define ROWS_ (B_*C_)          // 4096
#define KSEG_ 8

// ---------------- scratch ----------------
__device__ __nv_bfloat16 d_xh0[ROWS_*N_];
__device__ __nv_bfloat16 d_xl0[ROWS_*N_];
__device__ __nv_bfloat16 d_xh1[ROWS_*N_];
__device__ __nv_bfloat16 d_xl1[ROWS_*N_];
__device__ __nv_bfloat16 d_ftabh[2*MODES_*N_];
__device__ __nv_bfloat16 d_ftabl[2*MODES_*N_];
__device__ __nv_bfloat16 d_itabh[2*MODES_*N_];
__device__ __nv_bfloat16 d_itabl[2*MODES_*N_];
__device__ float d_hg[L_*B_*KM_];
__device__ float d_hl[L_*B_*KM_];
__device__ float d_xft[ROWS_*2*MODES_];
__device__ float d_dftp[KSEG_*ROWS_*2*MODES_];   // dft partials
__device__ __nv_bfloat16 d_Ahg[B_*C_*KAUG_];
__device__ __nv_bfloat16 d_Alg[B_*C_*KAUG_];
__device__ __nv_bfloat16 d_w1h[CC_];             // fc1_w transposed [h][c], hi
__device__ __nv_bfloat16 d_w1l[CC_];             // lo

__device__ __forceinline__ float gelu_f(float x) {
    return 0.5f * x * (1.0f + erff(x * 0.70710678118654752f));
}

// ---------------- mma/ldmatrix/cp.async helpers ----------------
__device__ __forceinline__ uint32_t s2u(const void* p) {
    return (uint32_t)__cvta_generic_to_shared(p);
}
__device__ __forceinline__ void ldm_x4(uint32_t* r, uint32_t addr) {
    asm volatile("ldmatrix.sync.aligned.m8n8.x4.shared.b16 {%0,%1,%2,%3}, [%4];"
                 : "=r"(r[0]), "=r"(r[1]), "=r"(r[2]), "=r"(r[3]) : "r"(addr));
}
__device__ __forceinline__ void ldm_x4t(uint32_t* r, uint32_t addr) {
    asm volatile("ldmatrix.sync.aligned.m8n8.x4.trans.shared.b16 {%0,%1,%2,%3}, [%4];"
                 : "=r"(r[0]), "=r"(r[1]), "=r"(r[2]), "=r"(r[3]) : "r"(addr));
}
__device__ __forceinline__ void ldm_x2t(uint32_t* r, uint32_t addr) {
    asm volatile("ldmatrix.sync.aligned.m8n8.x2.trans.shared.b16 {%0,%1}, [%2];"
                 : "=r"(r[0]), "=r"(r[1]) : "r"(addr));
}
__device__ __forceinline__ void mma_bf16(float* d, const uint32_t* a,
                                         uint32_t b0, uint32_t b1) {
    asm volatile("mma.sync.aligned.m16n8k16.row.col.f32.bf16.bf16.f32 "
                 "{%0,%1,%2,%3}, {%4,%5,%6,%7}, {%8,%9}, {%0,%1,%2,%3};"
                 : "+f"(d[0]), "+f"(d[1]), "+f"(d[2]), "+f"(d[3])
                 : "r"(a[0]), "r"(a[1]), "r"(a[2]), "r"(a[3]), "r"(b0), "r"(b1));
}
__device__ __forceinline__ void cpa(uint32_t dst, const void* src) {
    asm volatile("cp.async.cg.shared.global [%0], [%1], 16;" :: "r"(dst), "l"(src));
}
#define CPA_COMMIT() asm volatile("cp.async.commit_group;")
#define CPA_WAIT(n)  asm volatile("cp.async.wait_group %0;" :: "n"(n))

__device__ __forceinline__ void bsplit(float v, __nv_bfloat16& h, __nv_bfloat16& l) {
    h = __float2bfloat16_rn(v);
    l = __float2bfloat16_rn(v - __bfloat162float(h));
}

// ---------------- tables ----------------
__global__ void table_kernel()
{
    int idx = blockIdx.x * 256 + threadIdx.x;
    if (idx >= 2*MODES_*N_) return;
    int m  = idx / N_;
    int n  = idx - m * N_;
    int mm = (m < MODES_) ? m : m - MODES_;
    float ang = 6.283185307179586f * (float)((mm * n) & (N_ - 1)) / (float)N_;
    float s, c;
    sincosf(ang, &s, &c);
    float fv = (m < MODES_) ? c : -s;
    __nv_bfloat16 h, l;
    bsplit(fv, h, l);
    d_ftabh[idx] = h;
    d_ftabl[idx] = l;
    float v;
    if (m < MODES_) v = (((m == 0) ? 1.0f : 2.0f) / (float)N_) * c;
    else            v = (mm == 0) ? 0.0f : (-2.0f / (float)N_) * s;
    bsplit(v, h, l);
    d_itabh[idx] = h;
    d_itabl[idx] = l;
}

// ---------------- w1 transpose + split (once) ----------------
__global__ void w1split_kernel(const float* __restrict__ w1)
{
    int idx = blockIdx.x * 256 + threadIdx.x;   // CC_
    int c = idx >> 7, h = idx & 127;
    float v = w1[idx];                           // w1[c][h]
    __nv_bfloat16 hh, ll;
    bsplit(v, hh, ll);
    d_w1h[h * C_ + c] = hh;
    d_w1l[h * C_ + c] = ll;
}

// ---------------- fc0 -> xh0/xl0 (vectorized: 8 n per thread) ----------------
__global__ void fc0_kernel(const float* __restrict__ x,
                           const float* __restrict__ w,
                           const float* __restrict__ bias)
{
    int idx = blockIdx.x * 256 + threadIdx.x;   // over ROWS_*N_/8
    int b = idx / (C_ * (N_ / 8));
    int rem = idx - b * (C_ * (N_ / 8));
    int c = rem / (N_ / 8);
    int n8 = rem - c * (N_ / 8);

    float w0 = w[c], w1v = w[C_ + c], w2v = w[2 * C_ + c], bz = bias[c];

    const float4* xp4 = (const float4*)(x + ((size_t)b * N_ + n8 * 8) * 3);
    float4 q0 = xp4[0], q1 = xp4[1], q2 = xp4[2];
    float4 q3 = xp4[3], q4 = xp4[4], q5 = xp4[5];
    float vv[24] = {q0.x,q0.y,q0.z,q0.w, q1.x,q1.y,q1.z,q1.w,
                    q2.x,q2.y,q2.z,q2.w, q3.x,q3.y,q3.z,q3.w,
                    q4.x,q4.y,q4.z,q4.w, q5.x,q5.y,q5.z,q5.w};

    union { __nv_bfloat16 bb[8]; uint4 u; } uh, ul;
    #pragma unroll
    for (int j = 0; j < 8; j++) {
        float v = bz + vv[j*3] * w0 + vv[j*3+1] * w1v + vv[j*3+2] * w2v;
        bsplit(v, uh.bb[j], ul.bb[j]);
    }
    size_t o = ((size_t)(b * C_ + c)) * N_ + n8 * 8;
    *(uint4*)&d_xh0[o] = uh.u;
    *(uint4*)&d_xl0[o] = ul.u;
}

// ---------------- hg/hl: 256 threads, 4-way j-segment split ----------------
__global__ void hgl_kernel(const float* __restrict__ y,
                           const float* __restrict__ g1w, const float* __restrict__ g1b,
                           const float* __restrict__ l1w, const float* __restrict__ l1b)
{
    int b = blockIdx.x, which = blockIdx.y, l = blockIdx.z;
    __shared__ float ys[KIN_];
    __shared__ float red[4][KM_];
    int t = threadIdx.x;
    int k = t & 63, seg = t >> 6;
    for (int j = t; j < KIN_; j += 256) ys[j] = y[b * KIN_ + j];
    __syncthreads();
    const float* w = (which ? l1w : g1w) + (size_t)l * KIN_ * KM_ + seg * 64 * KM_;
    float acc = 0.0f;
    #pragma unroll 16
    for (int j = 0; j < 64; j++) acc += ys[seg * 64 + j] * w[j * KM_ + k];
    red[seg][k] = acc;
    __syncthreads();
    if (t < KM_) {
        const float* bb = (which ? l1b : g1b) + l * KM_;
        float v = red[0][t] + red[1][t] + red[2][t] + red[3][t] + bb[t];
        float g = gelu_f(v);
        float* dst = which ? d_hl : d_hg;
        dst[l * B_ * KM_ + b * KM_ + t] = g;
    }
}

// ---------------- forward DFT via mma.sync bf16x3, cp.async double-buffered ----------------
#define DFT_AH 0
#define DFT_AL 20480
#define DFT_BH 40960
#define DFT_BL 51200
#define DFT_SM 61440
#define DFT_ABUF 10240
#define DFT_BBUF 5120

__global__ void __launch_bounds__(256) dft_mma_kernel(int in_x1)
{
    extern __shared__ char smem[];
    uint32_t sb = s2u(smem);
    const __nv_bfloat16* __restrict__ xh = in_x1 ? d_xh1 : d_xh0;
    const __nv_bfloat16* __restrict__ xl = in_x1 ? d_xl1 : d_xl0;

    int r0 = blockIdx.x * 128;
    int K0 = blockIdx.y * (N_ / KSEG_);
    int t = threadIdx.x, wid = t >> 5, lane = t & 31;

    float acc[8][4];
    #pragma unroll
    for (int j = 0; j < 8; j++)
        #pragma unroll
        for (int q = 0; q < 4; q++) acc[j][q] = 0.0f;

    auto stage = [&](int c, int bf) {
        #pragma unroll
        for (int i = 0; i < 2; i++) {
            int f = t + 256 * i;
            int o = f >> 2, q = f & 3;
            size_t g = (size_t)(r0 + o) * N_ + K0 + c * 32 + q * 8;
            cpa(sb + DFT_AH + bf * DFT_ABUF + o * 80 + q * 16, xh + g);
            cpa(sb + DFT_AL + bf * DFT_ABUF + o * 80 + q * 16, xl + g);
        }
        {
            int j = t >> 2, q = t & 3;
            size_t g = (size_t)j * N_ + K0 + c * 32 + q * 8;
            cpa(sb + DFT_BH + bf * DFT_BBUF + j * 80 + q * 16, d_ftabh + g);
            cpa(sb + DFT_BL + bf * DFT_BBUF + j * 80 + q * 16, d_ftabl + g);
        }
    };

    stage(0, 0);
    CPA_COMMIT();

    const int NCHUNK = (N_ / KSEG_) / 32;   // 16
    for (int c = 0; c < NCHUNK; c++) {
        int bf = c & 1;
        if (c < NCHUNK - 1) {
            stage(c + 1, bf ^ 1);
            CPA_COMMIT();
            CPA_WAIT(1);
        } else {
            CPA_WAIT(0);
        }
        __syncthreads();

        #pragma unroll
        for (int ks = 0; ks < 32; ks += 16) {
            uint32_t ah[4], al[4];
            {
                int r = wid * 16 + (lane & 15);
                uint32_t off = (uint32_t)r * 80 + (uint32_t)(ks + ((lane >> 4) << 3)) * 2;
                ldm_x4(ah, sb + DFT_AH + bf * DFT_ABUF + off);
                ldm_x4(al, sb + DFT_AL + bf * DFT_ABUF + off);
            }
            #pragma unroll
            for (int nb = 0; nb < 4; nb++) {
                int jr = nb * 16 + (lane & 7) + ((lane >> 4) << 3);
                int kc = ks + (((lane >> 3) & 1) << 3);
                uint32_t off = (uint32_t)jr * 80 + (uint32_t)kc * 2;
                uint32_t bh[4], bl[4];
                ldm_x4(bh, sb + DFT_BH + bf * DFT_BBUF + off);
                ldm_x4(bl, sb + DFT_BL + bf * DFT_BBUF + off);
                mma_bf16(acc[nb*2],     ah, bh[0], bh[1]);
                mma_bf16(acc[nb*2],     ah, bl[0], bl[1]);
                mma_bf16(acc[nb*2],     al, bh[0], bh[1]);
                mma_bf16(acc[nb*2 + 1], ah, bh[2], bh[3]);
                mma_bf16(acc[nb*2 + 1], ah, bl[2], bl[3]);
                mma_bf16(acc[nb*2 + 1], al, bh[2], bh[3]);
            }
        }
        __syncthreads();
    }

    float* dst = d_dftp + ((size_t)blockIdx.y * ROWS_ + r0) * 64;
    int row = wid * 16 + (lane >> 2);
    #pragma unroll
    for (int j = 0; j < 8; j++) {
        int col = j * 8 + (lane & 3) * 2;
        *(float2*)&dst[(size_t)row * 64 + col]       = make_float2(acc[j][0], acc[j][1]);
        *(float2*)&dst[(size_t)(row + 8) * 64 + col] = make_float2(acc[j][2], acc[j][3]);
    }
}

// ---------------- FUSED dft_reduce + wlin (independent work, one launch) ----------------
__global__ void __launch_bounds__(256) reduce_wlin_kernel(
    const float* __restrict__ l2w_l, const float* __restrict__ l2b_l, int l)
{
    __shared__ float hs[B_ * KM_];
    int t = threadIdx.x;
    if (blockIdx.x < (ROWS_ * 64) / 256) {
        int idx = blockIdx.x * 256 + t;
        float s = 0.0f;
        #pragma unroll
        for (int seg = 0; seg < KSEG_; seg++) s += d_dftp[(size_t)seg * ROWS_ * 64 + idx];
        d_xft[idx] = s;
        return;
    }
    // ---- wlin part ----
    int wb = blockIdx.x - (ROWS_ * 64) / 256;
    for (int i = t; i < B_ * KM_; i += 256) hs[i] = d_hl[l * B_ * KM_ + i];
    __syncthreads();
    int col = wb * 256 + t;
    int o = col >> 7, ii = col & 127;
    float bias = l2b_l[col];
    float acc[B_];
    #pragma unroll
    for (int b = 0; b < B_; b++) acc[b] = bias;
    #pragma unroll 4
    for (int k = 0; k < KM_; k++) {
        float g = l2w_l[(size_t)k * CC_ + col];
        #pragma unroll
        for (int b = 0; b < B_; b++) acc[b] += hs[b * KM_ + k] * g;
    }
    #pragma unroll
    for (int b = 0; b < B_; b++) {
        __nv_bfloat16 h, lo;
        bsplit(acc[b], h, lo);
        size_t idx = ((size_t)(b * C_ + o)) * KAUG_ + ii;
        d_Ahg[idx] = h;
        d_Alg[idx] = lo;
    }
}

// ---------------- FUSED wspec + spectral contraction, cp.async depth-4 G ring ----------------
// grid (C_): blockIdx.x = o. Full i-range per CTA (64 p2-iters).
// Epilogue writes final om bf16 hi/lo DIRECTLY into d_Ahg/d_Alg cols 128..191.
#define WS_AH 0
#define WS_AL 5120
#define WS_GH 10240
#define WS_GL 20480
#define WS_XS 30720
#define WS_GF 47104
#define WS_GFSTG 16640
#define WS_RING 4
#define WS_SM (WS_GF + WS_RING * WS_GFSTG)   // 113664

__global__ void __launch_bounds__(256) wspec_contract_kernel(
    const float* __restrict__ g2w_l, const float* __restrict__ g2b_l, int l)
{
    extern __shared__ char smem[];
    __nv_bfloat16* Ahs = (__nv_bfloat16*)(smem + WS_AH);   // [32][80]
    __nv_bfloat16* Als = (__nv_bfloat16*)(smem + WS_AL);
    __nv_bfloat16* Gh  = (__nv_bfloat16*)(smem + WS_GH);   // [2][80][32]
    __nv_bfloat16* Gl  = (__nv_bfloat16*)(smem + WS_GL);
    float*         Xs  = (float*)(smem + WS_XS);           // [2][32][64]
    uint32_t sb = s2u(smem);

    int o = blockIdx.x;
    int t = threadIdx.x, lane = t & 31, wid = t >> 5;
    int iw = wid & 1, nq = wid >> 1;   // i-parity, mode-quarter

    // stage A = [hg | 1 | 0...] split hi/lo
    for (int idx = t; idx < 32 * 80; idx += 256) {
        int b = idx / 80, k = idx - b * 80;
        float v = (k < 64) ? d_hg[l * B_ * KM_ + b * 64 + k]
                           : (k == 64 ? 1.0f : 0.0f);
        __nv_bfloat16 h, lo;
        bsplit(v, h, lo);
        Ahs[b * 80 + k] = h;
        Als[b * 80 + k] = lo;
    }
    // zero G rows 65..79 (both parities) once
    for (int idx = t; idx < 2 * 15 * 32; idx += 256) {
        int p = idx / (15 * 32), r = idx - p * (15 * 32);
        int row = 65 + (r >> 5), m = r & 31;
        Gh[(p * 80 + row) * 32 + m] = __float2bfloat16(0.0f);
        Gl[(p * 80 + row) * 32 + m] = __float2bfloat16(0.0f);
    }
    __syncthreads();

    // preload A fragments for BOTH m16 halves (constant over i)
    uint32_t afh[2][5][4], afl[2][5][4];
    #pragma unroll
    for (int mi = 0; mi < 2; mi++)
        #pragma unroll
        for (int kt = 0; kt < 5; kt++) {
            int r = mi * 16 + (lane & 15);
            uint32_t off = ((uint32_t)r * 80 + kt * 16 + ((lane >> 4) << 3)) * 2;
            ldm_x4(afh[mi][kt], sb + WS_AH + off);
            ldm_x4(afl[mi][kt], sb + WS_AL + off);
        }

    float accr[2][4], acci[2][4];
    #pragma unroll
    for (int mi = 0; mi < 2; mi++)
        #pragma unroll
        for (int q = 0; q < 4; q++) { accr[mi][q] = 0.0f; acci[mi][q] = 0.0f; }

    // cp.async G-stage issuer: 1040 16B chunks (2 i x 65 rows x 8 segs)
    auto issue_g = [&](int p2, int buf) {
        #pragma unroll
        for (int j = 0; j < 5; j++) {
            int idx = t + j * 256;
            if (idx < 1040) {
                int p = (idx >= 520) ? 1 : 0;
                int r = idx - p * 520;
                int row = r >> 3, seg = r & 7;
                int i = p2 * 2 + p;
                const float* src = (row < 64)
                    ? (g2w_l + (size_t)row * OUT_ + (size_t)i * (C_ * MODES_) + o * MODES_ + seg * 4)
                    : (g2b_l + (size_t)i * (C_ * MODES_) + o * MODES_ + seg * 4);
                cpa(sb + WS_GF + buf * WS_GFSTG + p * 8320 + row * 128 + seg * 16, src);
            }
        }
        CPA_COMMIT();
    };

    float4 x_r[4];
    auto xprefetch = [&](int p2) {
        #pragma unroll
        for (int j = 0; j < 4; j++) {
            int idx = t + j * 256;
            int p = idx >> 9, r = idx & 511;
            int b = r >> 4, seg = r & 15;
            int i = p2 * 2 + p;
            x_r[j] = *(const float4*)&d_xft[((size_t)(b * C_) + i) * 64 + seg * 4];
        }
    };

    const int NIT = 64;
    issue_g(0, 0);
    issue_g(1, 1);
    issue_g(2, 2);
    issue_g(3, 3);
    xprefetch(0);

    for (int c = 0; c < NIT; c++) {
        CPA_WAIT(3);          // stage c landed (3 stages still in flight)
        __syncthreads();      // + prev MMA done reading Gh/Gl

        // split G fp32 (ring buf c%4) -> Gh/Gl bf16; store X regs -> Xs
        {
            int buf = c % WS_RING;
            #pragma unroll
            for (int j = 0; j < 5; j++) {
                int idx = t + j * 256;
                if (idx < 1040) {
                    int p = (idx >= 520) ? 1 : 0;
                    int r = idx - p * 520;
                    int row = r >> 3, seg = r & 7;
                    float4 v = *(float4*)(smem + WS_GF + buf * WS_GFSTG + p * 8320 + row * 128 + seg * 16);
                    __nv_bfloat16 h0,l0,h1,l1,h2,l2,h3,l3;
                    bsplit(v.x,h0,l0); bsplit(v.y,h1,l1);
                    bsplit(v.z,h2,l2); bsplit(v.w,h3,l3);
                    int gbase = (p * 80 + row) * 32 + seg * 4;
                    *(__nv_bfloat162*)&Gh[gbase]     = __halves2bfloat162(h0, h1);
                    *(__nv_bfloat162*)&Gh[gbase + 2] = __halves2bfloat162(h2, h3);
                    *(__nv_bfloat162*)&Gl[gbase]     = __halves2bfloat162(l0, l1);
                    *(__nv_bfloat162*)&Gl[gbase + 2] = __halves2bfloat162(l2, l3);
                }
            }
            #pragma unroll
            for (int j = 0; j < 4; j++) {
                int idx = t + j * 256;
                int p = idx >> 9, r = idx & 511;
                int b = r >> 4, seg = r & 15;
                *(float4*)&Xs[(p * 32 + b) * 64 + seg * 4] = x_r[j];
            }
        }
        __syncthreads();      // split visible; ring buf c%4 free

        if (c < NIT - WS_RING) issue_g(c + WS_RING, (c + WS_RING) % WS_RING);
        else                   CPA_COMMIT();   // keep group accounting uniform
        if (c < NIT - 1) xprefetch(c + 1);

        // W = A x G (bf16x3): each warp covers 32 b x 8 modes, B-frags read ONCE
        float W[2][4];
        #pragma unroll
        for (int mi = 0; mi < 2; mi++)
            #pragma unroll
            for (int q = 0; q < 4; q++) W[mi][q] = 0.0f;

        uint32_t gbase_h = sb + WS_GH + (uint32_t)iw * 80 * 32 * 2;
        uint32_t gbase_l = sb + WS_GL + (uint32_t)iw * 80 * 32 * 2;
        #pragma unroll
        for (int kt = 0; kt < 5; kt++) {
            uint32_t off = ((uint32_t)(kt * 16 + (lane & 15)) * 32 + nq * 8) * 2;
            uint32_t bh[2], bl[2];
            ldm_x2t(bh, gbase_h + off);
            ldm_x2t(bl, gbase_l + off);
            #pragma unroll
            for (int mi = 0; mi < 2; mi++) {
                mma_bf16(W[mi], afh[mi][kt], bh[0], bh[1]);
                mma_bf16(W[mi], afh[mi][kt], bl[0], bl[1]);
                mma_bf16(W[mi], afl[mi][kt], bh[0], bh[1]);
            }
        }

        int m0 = nq * 8 + (lane & 3) * 2;
        #pragma unroll
        for (int mi = 0; mi < 2; mi++) {
            int b0 = mi * 16 + (lane >> 2);
            float2 xr0 = *(float2*)&Xs[(iw * 32 + b0) * 64 + m0];
            float2 xi0 = *(float2*)&Xs[(iw * 32 + b0) * 64 + 32 + m0];
            float2 xr1 = *(float2*)&Xs[(iw * 32 + b0 + 8) * 64 + m0];
            float2 xi1 = *(float2*)&Xs[(iw * 32 + b0 + 8) * 64 + 32 + m0];
            accr[mi][0] += W[mi][0] * xr0.x;  accr[mi][1] += W[mi][1] * xr0.y;
            accr[mi][2] += W[mi][2] * xr1.x;  accr[mi][3] += W[mi][3] * xr1.y;
            acci[mi][0] += W[mi][0] * xi0.x;  acci[mi][1] += W[mi][1] * xi0.y;
            acci[mi][2] += W[mi][2] * xi1.x;  acci[mi][3] += W[mi][3] * xi1.y;
        }
    }

    // reduce across iw parities (reuse Xs region), write bf16 hi/lo DIRECTLY
    // into d_Ahg/d_Alg cols 128..191 (replaces asplit kernel)
    __syncthreads();
    int m0 = nq * 8 + (lane & 3) * 2;
    if (iw == 1) {
        #pragma unroll
        for (int mi = 0; mi < 2; mi++) {
            int b0 = mi * 16 + (lane >> 2);
            Xs[b0 * 64 + m0]              = accr[mi][0];
            Xs[b0 * 64 + m0 + 1]          = accr[mi][1];
            Xs[(b0 + 8) * 64 + m0]        = accr[mi][2];
            Xs[(b0 + 8) * 64 + m0 + 1]    = accr[mi][3];
            Xs[b0 * 64 + 32 + m0]         = acci[mi][0];
            Xs[b0 * 64 + 32 + m0 + 1]     = acci[mi][1];
            Xs[(b0 + 8) * 64 + 32 + m0]   = acci[mi][2];
            Xs[(b0 + 8) * 64 + 32 + m0+1] = acci[mi][3];
        }
    }
    __syncthreads();
    if (iw == 0) {
        #pragma unroll
        for (int mi = 0; mi < 2; mi++) {
            int b0 = mi * 16 + (lane >> 2);
            float r00 = accr[mi][0] + Xs[b0 * 64 + m0];
            float r01 = accr[mi][1] + Xs[b0 * 64 + m0 + 1];
            float r10 = accr[mi][2] + Xs[(b0 + 8) * 64 + m0];
            float r11 = accr[mi][3] + Xs[(b0 + 8) * 64 + m0 + 1];
            float i00 = acci[mi][0] + Xs[b0 * 64 + 32 + m0];
            float i01 = acci[mi][1] + Xs[b0 * 64 + 32 + m0 + 1];
            float i10 = acci[mi][2] + Xs[(b0 + 8) * 64 + 32 + m0];
            float i11 = acci[mi][3] + Xs[(b0 + 8) * 64 + 32 + m0 + 1];

            __nv_bfloat16 h0,l0,h1,l1;
            size_t A0 = ((size_t)(b0 * C_ + o)) * KAUG_ + C_;
            size_t A1 = ((size_t)((b0 + 8) * C_ + o)) * KAUG_ + C_;

            bsplit(r00,h0,l0); bsplit(r01,h1,l1);
            *(__nv_bfloat162*)&d_Ahg[A0 + m0] = __halves2bfloat162(h0, h1);
            *(__nv_bfloat162*)&d_Alg[A0 + m0] = __halves2bfloat162(l0, l1);
            bsplit(r10,h0,l0); bsplit(r11,h1,l1);
            *(__nv_bfloat162*)&d_Ahg[A1 + m0] = __halves2bfloat162(h0, h1);
            *(__nv_bfloat162*)&d_Alg[A1 + m0] = __halves2bfloat162(l0, l1);
            bsplit(i00,h0,l0); bsplit(i01,h1,l1);
            *(__nv_bfloat162*)&d_Ahg[A0 + MODES_ + m0] = __halves2bfloat162(h0, h1);
            *(__nv_bfloat162*)&d_Alg[A0 + MODES_ + m0] = __halves2bfloat162(l0, l1);
            bsplit(i10,h0,l0); bsplit(i11,h1,l1);
            *(__nv_bfloat162*)&d_Ahg[A1 + MODES_ + m0] = __halves2bfloat162(h0, h1);
            *(__nv_bfloat162*)&d_Alg[A1 + MODES_ + m0] = __halves2bfloat162(l0, l1);
        }
    }
}

// ---------------- layer GEMM via mma.sync bf16x3, cp.async double-buffered ----------------
#define LAY_AH 0
#define LAY_AL 20480
#define LAY_BH 40960
#define LAY_BL 58368
#define LAY_SM 75776
#define LAY_ABUF 10240
#define LAY_BBUF 8704

__global__ void __launch_bounds__(256, 2) layer_mma_kernel(int in_x1, int do_gelu)
{
    extern __shared__ char smem[];
    uint32_t sb = s2u(smem);
    const __nv_bfloat16* __restrict__ xh = in_x1 ? d_xh1 : d_xh0;
    const __nv_bfloat16* __restrict__ xl = in_x1 ? d_xl1 : d_xl0;
    __nv_bfloat16* __restrict__ yh = in_x1 ? d_xh0 : d_xh1;
    __nv_bfloat16* __restrict__ yl = in_x1 ? d_xl0 : d_xl1;

    int b = blockIdx.y, n0 = blockIdx.x * 128;
    int t = threadIdx.x, wid = t >> 5, lane = t & 31;
    int wm = wid & 3, wn = wid >> 2;

    const __nv_bfloat16* Ahb = d_Ahg + (size_t)b * C_ * KAUG_;
    const __nv_bfloat16* Alb = d_Alg + (size_t)b * C_ * KAUG_;
    size_t xbase = (size_t)b * C_ * N_;

    float acc[2][8][4];
    #pragma unroll
    for (int mi = 0; mi < 2; mi++)
        #pragma unroll
        for (int j = 0; j < 8; j++)
            #pragma unroll
            for (int q = 0; q < 4; q++) acc[mi][j][q] = 0.0f;

    auto stage = [&](int c, int bf) {
        #pragma unroll
        for (int i = 0; i < 2; i++) {
            int f = t + 256 * i;
            int o = f >> 2, q = f & 3;
            size_t g = (size_t)o * KAUG_ + c * 32 + q * 8;
            cpa(sb + LAY_AH + bf * LAY_ABUF + o * 80 + q * 16, Ahb + g);
            cpa(sb + LAY_AL + bf * LAY_ABUF + o * 80 + q * 16, Alb + g);
        }
        #pragma unroll
        for (int i = 0; i < 2; i++) {
            int f = t + 256 * i;
            int kk = f >> 4, q = f & 15;
            int kg = c * 32 + kk;
            const __nv_bfloat16 *rh, *rl;
            if (kg < C_) {
                rh = xh + xbase + (size_t)kg * N_ + n0;
                rl = xl + xbase + (size_t)kg * N_ + n0;
            } else {
                rh = d_itabh + (size_t)(kg - C_) * N_ + n0;
                rl = d_itabl + (size_t)(kg - C_) * N_ + n0;
            }
            cpa(sb + LAY_BH + bf * LAY_BBUF + kk * 272 + q * 16, rh + q * 8);
            cpa(sb + LAY_BL + bf * LAY_BBUF + kk * 272 + q * 16, rl + q * 8);
        }
    };

    stage(0, 0);
    CPA_COMMIT();

    for (int c = 0; c < 6; c++) {
        int bf = c & 1;
        if (c < 5) {
            stage(c + 1, bf ^ 1);
            CPA_COMMIT();
            CPA_WAIT(1);
        } else {
            CPA_WAIT(0);
        }
        __syncthreads();

        #pragma unroll
        for (int ks = 0; ks < 32; ks += 16) {
            uint32_t ah[2][4], al[2][4];
            #pragma unroll
            for (int mi = 0; mi < 2; mi++) {
                int r = wm * 32 + mi * 16 + (lane & 15);
                uint32_t off = (uint32_t)r * 80 + (uint32_t)(ks + ((lane >> 4) << 3)) * 2;
                ldm_x4(ah[mi], sb + LAY_AH + bf * LAY_ABUF + off);
                ldm_x4(al[mi], sb + LAY_AL + bf * LAY_ABUF + off);
            }
            #pragma unroll
            for (int nb = 0; nb < 4; nb++) {
                int kr = ks + (lane & 15);
                int nc = wn * 64 + nb * 16 + ((lane >> 4) << 3);
                uint32_t off = (uint32_t)kr * 272 + (uint32_t)nc * 2;
                uint32_t bh[4], bl[4];
                ldm_x4t(bh, sb + LAY_BH + bf * LAY_BBUF + off);
                ldm_x4t(bl, sb + LAY_BL + bf * LAY_BBUF + off);
                #pragma unroll
                for (int mi = 0; mi < 2; mi++) {
                    mma_bf16(acc[mi][nb*2],     ah[mi], bh[0], bh[1]);
                    mma_bf16(acc[mi][nb*2],     ah[mi], bl[0], bl[1]);
                    mma_bf16(acc[mi][nb*2],     al[mi], bh[0], bh[1]);
                    mma_bf16(acc[mi][nb*2 + 1], ah[mi], bh[2], bh[3]);
                    mma_bf16(acc[mi][nb*2 + 1], ah[mi], bl[2], bl[3]);
                    mma_bf16(acc[mi][nb*2 + 1], al[mi], bh[2], bh[3]);
                }
            }
        }
        __syncthreads();
    }

    #pragma unroll
    for (int mi = 0; mi < 2; mi++) {
        int o = wm * 32 + mi * 16 + (lane >> 2);
        #pragma unroll
        for (int j = 0; j < 8; j++) {
            int col = n0 + wn * 64 + j * 8 + (lane & 3) * 2;
            float v0 = acc[mi][j][0], v1 = acc[mi][j][1];
            float v2 = acc[mi][j][2], v3 = acc[mi][j][3];
            if (do_gelu) {
                v0 = gelu_f(v0); v1 = gelu_f(v1);
                v2 = gelu_f(v2); v3 = gelu_f(v3);
            }
            __nv_bfloat16 h0, l0, h1, l1, h2, l2, h3, l3;
            bsplit(v0, h0, l0); bsplit(v1, h1, l1);
            bsplit(v2, h2, l2); bsplit(v3, h3, l3);
            size_t p0 = xbase + (size_t)o * N_ + col;
            size_t p1 = xbase + (size_t)(o + 8) * N_ + col;
            *(__nv_bfloat162*)&yh[p0] = __halves2bfloat162(h0, h1);
            *(__nv_bfloat162*)&yl[p0] = __halves2bfloat162(l0, l1);
            *(__nv_bfloat162*)&yh[p1] = __halves2bfloat162(h2, h3);
            *(__nv_bfloat162*)&yl[p1] = __halves2bfloat162(l2, l3);
        }
    }
}

// ---------------- final MLP via mma.sync bf16x3 ----------------
#define FIN_OFF LAY_SM
#define FIN_SM  (LAY_SM + 2048)

__global__ void __launch_bounds__(256, 2) final_mma_kernel(
    const float* __restrict__ b1, const float* __restrict__ w2,
    const float* __restrict__ b2, const float* __restrict__ wx,
    float* __restrict__ out)
{
    extern __shared__ char smem[];
    uint32_t sb = s2u(smem);
    float* fin = (float*)(smem + FIN_OFF);   // [4][128]

    int b = blockIdx.y, n0 = blockIdx.x * 128;
    int t = threadIdx.x, wid = t >> 5, lane = t & 31;
    int wm = wid & 3, wn = wid >> 2;
    size_t xbase = (size_t)b * C_ * N_;

    float acc[2][8][4];
    #pragma unroll
    for (int mi = 0; mi < 2; mi++)
        #pragma unroll
        for (int j = 0; j < 8; j++)
            #pragma unroll
            for (int q = 0; q < 4; q++) acc[mi][j][q] = 0.0f;

    auto stage = [&](int c, int bf) {
        #pragma unroll
        for (int i = 0; i < 2; i++) {
            int f = t + 256 * i;
            int o = f >> 2, q = f & 3;
            size_t g = (size_t)o * C_ + c * 32 + q * 8;
            cpa(sb + LAY_AH + bf * LAY_ABUF + o * 80 + q * 16, d_w1h + g);
            cpa(sb + LAY_AL + bf * LAY_ABUF + o * 80 + q * 16, d_w1l + g);
        }
        #pragma unroll
        for (int i = 0; i < 2; i++) {
            int f = t + 256 * i;
            int kk = f >> 4, q = f & 15;
            int kg = c * 32 + kk;
            cpa(sb + LAY_BH + bf * LAY_BBUF + kk * 272 + q * 16,
                d_xh0 + xbase + (size_t)kg * N_ + n0 + q * 8);
            cpa(sb + LAY_BL + bf * LAY_BBUF + kk * 272 + q * 16,
                d_xl0 + xbase + (size_t)kg * N_ + n0 + q * 8);
        }
    };

    stage(0, 0);
    CPA_COMMIT();

    for (int c = 0; c < 4; c++) {
        int bf = c & 1;
        if (c < 3) {
            stage(c + 1, bf ^ 1);
            CPA_COMMIT();
            CPA_WAIT(1);
        } else {
            CPA_WAIT(0);
        }
        __syncthreads();

        #pragma unroll
        for (int ks = 0; ks < 32; ks += 16) {
            uint32_t ah[2][4], al[2][4];
            #pragma unroll
            for (int mi = 0; mi < 2; mi++) {
                int r = wm * 32 + mi * 16 + (lane & 15);
                uint32_t off = (uint32_t)r * 80 + (uint32_t)(ks + ((lane >> 4) << 3)) * 2;
                ldm_x4(ah[mi], sb + LAY_AH + bf * LAY_ABUF + off);
                ldm_x4(al[mi], sb + LAY_AL + bf * LAY_ABUF + off);
            }
            #pragma unroll
            for (int nb = 0; nb < 4; nb++) {
                int kr = ks + (lane & 15);
                int nc = wn * 64 + nb * 16 + ((lane >> 4) << 3);
                uint32_t off = (uint32_t)kr * 272 + (uint32_t)nc * 2;
                uint32_t bh[4], bl[4];
                ldm_x4t(bh, sb + LAY_BH + bf * LAY_BBUF + off);
                ldm_x4t(bl, sb + LAY_BL + bf * LAY_BBUF + off);
                #pragma unroll
                for (int mi = 0; mi < 2; mi++) {
                    mma_bf16(acc[mi][nb*2],     ah[mi], bh[0], bh[1]);
                    mma_bf16(acc[mi][nb*2],     ah[mi], bl[0], bl[1]);
                    mma_bf16(acc[mi][nb*2],     al[mi], bh[0], bh[1]);
                    mma_bf16(acc[mi][nb*2 + 1], ah[mi], bh[2], bh[3]);
                    mma_bf16(acc[mi][nb*2 + 1], ah[mi], bl[2], bl[3]);
                    mma_bf16(acc[mi][nb*2 + 1], al[mi], bh[2], bh[3]);
                }
            }
        }
        __syncthreads();
    }

    float p[8][2];
    #pragma unroll
    for (int j = 0; j < 8; j++) { p[j][0] = 0.0f; p[j][1] = 0.0f; }
    #pragma unroll
    for (int mi = 0; mi < 2; mi++) {
        int ra = wm * 32 + mi * 16 + (lane >> 2);
        float b1a = b1[ra], b1b = b1[ra + 8];
        float w2a = w2[ra], w2b = w2[ra + 8];
        #pragma unroll
        for (int j = 0; j < 8; j++) {
            p[j][0] += gelu_f(acc[mi][j][0] + b1a) * w2a + gelu_f(acc[mi][j][2] + b1b) * w2b;
            p[j][1] += gelu_f(acc[mi][j][1] + b1a) * w2a + gelu_f(acc[mi][j][3] + b1b) * w2b;
        }
    }
    #pragma unroll
    for (int off = 4; off < 32; off <<= 1) {
        #pragma unroll
        for (int j = 0; j < 8; j++) {
            p[j][0] += __shfl_xor_sync(0xFFFFFFFFu, p[j][0], off);
            p[j][1] += __shfl_xor_sync(0xFFFFFFFFu, p[j][1], off);
        }
    }
    if ((lane >> 2) == 0) {
        #pragma unroll
        for (int j = 0; j < 8; j++) {
            int col = wn * 64 + j * 8 + (lane & 3) * 2;
            fin[wm * 128 + col]     = p[j][0];
            fin[wm * 128 + col + 1] = p[j][1];
        }
    }
    __syncthreads();
    if (t < 128) {
        float v = fin[t] + fin[128 + t] + fin[256 + t] + fin[384 + t] + b2[0];
        out[(size_t)b * N_ + n0 + t] = v * wx[0];
    }
}

// ---------------- launch ----------------
extern "C" void kernel_launch(void* const* d_in, const int* in_sizes, int n_in,
                              void* d_out, int out_size)
{
    const float* x     = (const float*)d_in[0];
    const float* y     = (const float*)d_in[1];
    const float* fc0_w = (const float*)d_in[2];
    const float* fc0_b = (const float*)d_in[3];
    const float* g1_w  = (const float*)d_in[4];
    const float* g1_b  = (const float*)d_in[5];
    const float* g2_w  = (const float*)d_in[6];
    const float* g2_b  = (const float*)d_in[7];
    const float* l1_w  = (const float*)d_in[8];
    const float* l1_b  = (const float*)d_in[9];
    const float* l2_w  = (const float*)d_in[10];
    const float* l2_b  = (const float*)d_in[11];
    const float* fc1_w = (const float*)d_in[12];
    const float* fc1_b = (const float*)d_in[13];
    const float* fc2_w = (const float*)d_in[14];
    const float* fc2_b = (const float*)d_in[15];
    const float* wx    = (const float*)d_in[16];
    float* out = (float*)d_out;

    cudaFuncSetAttribute(dft_mma_kernel,
                         cudaFuncAttributeMaxDynamicSharedMemorySize, DFT_SM);
    cudaFuncSetAttribute(wspec_contract_kernel,
                         cudaFuncAttributeMaxDynamicSharedMemorySize, WS_SM);
    cudaFuncSetAttribute(layer_mma_kernel,
                         cudaFuncAttributeMaxDynamicSharedMemorySize, LAY_SM);
    cudaFuncSetAttribute(final_mma_kernel,
                         cudaFuncAttributeMaxDynamicSharedMemorySize, FIN_SM);

    table_kernel<<<(2*MODES_*N_)/256, 256>>>();
    w1split_kernel<<<CC_/256, 256>>>(fc1_w);
    fc0_kernel<<<(ROWS_*N_/8)/256, 256>>>(x, fc0_w, fc0_b);
    hgl_kernel<<<dim3(B_, 2, L_), 256>>>(y, g1_w, g1_b, l1_w, l1_b);

    for (int l = 0; l < L_; l++) {
        int in_x1 = l & 1;
        dft_mma_kernel<<<dim3(ROWS_/128, KSEG_), 256, DFT_SM>>>(in_x1);
        reduce_wlin_kernel<<<(ROWS_*64)/256 + CC_/256, 256>>>(
            l2_w + (size_t)l * KM_ * CC_, l2_b + (size_t)l * CC_, l);
        wspec_contract_kernel<<<C_, 256, WS_SM>>>(
            g2_w + (size_t)l * KM_ * OUT_, g2_b + (size_t)l * OUT_, l);
        layer_mma_kernel<<<dim3(N_/128, B_), 256, LAY_SM>>>(in_x1, (l < L_ - 1) ? 1 : 0);
    }

    final_mma_kernel<<<dim3(N_/128, B_), 256, FIN_SM>>>(fc1_b, fc2_w, fc2_b, wx, out);
}